// round 13
// baseline (speedup 1.0000x reference)
#include <cuda_runtime.h>
#include <cuda_fp16.h>
#include <cstdint>

#define TPB    128
#define MT     16          // points per tile
#define HDIM   256
#define DIN    16
#define DOUT   128
#define PITCHH 264         // sbuf pitch in halves; row stride 528B -> LDSM conflict-free
#define FPITCH 132         // float view pitch for layer-3 C / epilogue
#define ZPH    24          // z tile pitch in halves
#define BMAX   4096
#define NMAX   1100000

// ---------------- device scratch (no allocations allowed) ----------------
__device__ long long d_offs[BMAX + 1];
__device__ int       d_seg[NMAX];
__device__ float     d_sums[BMAX * DOUT];
__device__ float     d_emb[BMAX * DOUT];
// fp16 k16-chunk packed weights: index (kc*N + n)*4 + tg -> uint2
__device__ uint2     d_W1h[1  * HDIM * 4];
__device__ uint2     d_W2h[16 * HDIM * 4];
__device__ uint2     d_W3h[16 * DOUT * 4];

// ---------------- helpers ----------------
__device__ __forceinline__ unsigned h2u(float a, float b) {
    __half2 h = __floats2half2_rn(a, b);
    return *reinterpret_cast<unsigned*>(&h);
}

__device__ __forceinline__ void mma_f16(float4& d,
                                        unsigned a0, unsigned a1, unsigned a2, unsigned a3,
                                        unsigned b0, unsigned b1) {
    asm volatile(
        "mma.sync.aligned.m16n8k16.row.col.f32.f16.f16.f32 "
        "{%0,%1,%2,%3}, {%4,%5,%6,%7}, {%8,%9}, {%0,%1,%2,%3};"
        : "+f"(d.x), "+f"(d.y), "+f"(d.z), "+f"(d.w)
        : "r"(a0), "r"(a1), "r"(a2), "r"(a3), "r"(b0), "r"(b1));
}

__device__ __forceinline__ void ldsm_x4(unsigned& r0, unsigned& r1, unsigned& r2, unsigned& r3,
                                        unsigned addr) {
    asm volatile("ldmatrix.sync.aligned.m8n8.x4.shared.b16 {%0,%1,%2,%3}, [%4];"
                 : "=r"(r0), "=r"(r1), "=r"(r2), "=r"(r3) : "r"(addr));
}

__device__ __forceinline__ unsigned smem_u32(const void* p) {
    return (unsigned)__cvta_generic_to_shared(p);
}

__device__ __forceinline__ long long get_count(const void* np, int i, int is64) {
    if (is64) return ((const long long*)np)[i];
    return (long long)((const int*)np)[i];
}

// ---------------- small setup kernels ----------------
__global__ void scan_offsets(const void* __restrict__ np, int Bn) {
    __shared__ long long part[256];
    __shared__ int s_is64;
    if (threadIdx.x == 0) {
        const int* p32 = (const int*)np;
        int is64 = 1;
        for (int i = 1; i < 7 && i < 2 * Bn; i += 2)
            if (p32[i] != 0) is64 = 0;
        s_is64 = is64;
    }
    __syncthreads();
    const int is64 = s_is64;
    const int chunk = (Bn + 255) / 256;
    const int c0 = threadIdx.x * chunk;
    long long s = 0;
    for (int i = 0; i < chunk; i++) {
        int idx = c0 + i;
        if (idx < Bn) s += get_count(np, idx, is64);
    }
    part[threadIdx.x] = s;
    __syncthreads();
    if (threadIdx.x == 0) {
        long long r = 0;
        for (int i = 0; i < 256; i++) { long long t = part[i]; part[i] = r; r += t; }
    }
    __syncthreads();
    long long base = part[threadIdx.x];
    for (int i = 0; i < chunk; i++) {
        int idx = c0 + i;
        if (idx < Bn) {
            d_offs[idx] = base;
            base += get_count(np, idx, is64);
            if (idx == Bn - 1) d_offs[Bn] = base;
        }
    }
}

// fused: blocks [0,Bn) fill seg ids; blocks [Bn, ...) zero d_sums
__global__ void fill_seg_zero(int Bn) {
    int b = blockIdx.x;
    if (b < Bn) {
        long long lo = d_offs[b], hi = d_offs[b + 1];
        for (long long i = lo + threadIdx.x; i < hi; i += blockDim.x)
            d_seg[i] = b;
    } else {
        int i = (b - Bn) * blockDim.x + threadIdx.x;
        if (i < Bn * DOUT) d_sums[i] = 0.f;
    }
}

// pack weights into fp16 k16-chunk layout
__global__ void cvt_weights(const float* __restrict__ W1,
                            const float* __restrict__ W2,
                            const float* __restrict__ W3) {
    int i = blockIdx.x * 256 + threadIdx.x;   // launch >= 16384 threads
    if (i < 16 * HDIM * 4) {
        int tg = i & 3, n = (i >> 2) & (HDIM - 1), kc = i >> 10;
        int k = 16 * kc + 2 * tg;
        d_W2h[i] = make_uint2(h2u(W2[k * HDIM + n],       W2[(k + 1) * HDIM + n]),
                              h2u(W2[(k + 8) * HDIM + n], W2[(k + 9) * HDIM + n]));
    }
    if (i < 16 * DOUT * 4) {
        int tg = i & 3, n = (i >> 2) & (DOUT - 1), kc = i >> 9;
        int k = 16 * kc + 2 * tg;
        d_W3h[i] = make_uint2(h2u(W3[k * DOUT + n],       W3[(k + 1) * DOUT + n]),
                              h2u(W3[(k + 8) * DOUT + n], W3[(k + 9) * DOUT + n]));
    }
    if (i < 1 * HDIM * 4) {
        int tg = i & 3, n = i >> 2;
        int k = 2 * tg;
        d_W1h[i] = make_uint2(h2u(W1[k * HDIM + n],       W1[(k + 1) * HDIM + n]),
                              h2u(W1[(k + 8) * HDIM + n], W1[(k + 9) * HDIM + n]));
    }
}

// ---------------- in-register LN + ReLU -> fp16 smem (1m x 8n warp layout) ----------------
// 4 warps, 16 rows. acc[t]: {x,y}=row g cols n0+8t+2tg{,+1}; {z,w}=row g+8 same cols.
__device__ __forceinline__ void ln_relu_reg(
    float4 (&acc)[8], __half* __restrict__ sbufh,
    const float* __restrict__ bi, const float* __restrict__ ga, const float* __restrict__ be,
    float* __restrict__ red_s, float* __restrict__ red_q,
    float* __restrict__ s_m, float* __restrict__ s_r,
    int g, int tg, int n0, int nq, int tid)
{
    #pragma unroll
    for (int t = 0; t < 8; t++) {
        const float2 bb = *(const float2*)(bi + n0 + 8 * t + 2 * tg);
        acc[t].x += bb.x; acc[t].y += bb.y;
        acc[t].z += bb.x; acc[t].w += bb.y;
    }
    float sl = 0.f, ql = 0.f, sh = 0.f, qh = 0.f;
    #pragma unroll
    for (int t = 0; t < 8; t++) {
        float4 v = acc[t];
        sl += v.x + v.y;  ql += v.x * v.x + v.y * v.y;
        sh += v.z + v.w;  qh += v.z * v.z + v.w * v.w;
    }
    #pragma unroll
    for (int o = 1; o <= 2; o <<= 1) {
        sl += __shfl_xor_sync(0xffffffffu, sl, o);
        ql += __shfl_xor_sync(0xffffffffu, ql, o);
        sh += __shfl_xor_sync(0xffffffffu, sh, o);
        qh += __shfl_xor_sync(0xffffffffu, qh, o);
    }
    if (tg == 0) {
        red_s[g * 4 + nq]       = sl;
        red_q[g * 4 + nq]       = ql;
        red_s[(g + 8) * 4 + nq] = sh;
        red_q[(g + 8) * 4 + nq] = qh;
    }
    __syncthreads();
    if (tid < MT) {
        float ss = 0.f, qq = 0.f;
        #pragma unroll
        for (int w = 0; w < 4; w++) { ss += red_s[tid * 4 + w]; qq += red_q[tid * 4 + w]; }
        float mm = ss * (1.f / 256.f);
        s_m[tid] = mm;
        s_r[tid] = rsqrtf(qq * (1.f / 256.f) - mm * mm + 1e-5f);
    }
    __syncthreads();
    const float ml = s_m[g],     rl = s_r[g];
    const float mh = s_m[g + 8], rh = s_r[g + 8];
    #pragma unroll
    for (int t = 0; t < 8; t++) {
        const int col = n0 + 8 * t + 2 * tg;
        const float2 gg = *(const float2*)(ga + col);
        const float2 ee = *(const float2*)(be + col);
        unsigned lo = h2u(fmaxf((acc[t].x - ml) * rl * gg.x + ee.x, 0.f),
                          fmaxf((acc[t].y - ml) * rl * gg.y + ee.y, 0.f));
        unsigned hi = h2u(fmaxf((acc[t].z - mh) * rh * gg.x + ee.x, 0.f),
                          fmaxf((acc[t].w - mh) * rh * gg.y + ee.y, 0.f));
        *(unsigned*)(sbufh + g * PITCHH + col)       = lo;
        *(unsigned*)(sbufh + (g + 8) * PITCHH + col) = hi;
    }
    __syncthreads();
}

// ---------------- main fused persistent kernel (6 CTAs/SM, 16-pt tiles) ----------------
__global__ __launch_bounds__(TPB, 6)
void mlp_mma(const float* __restrict__ z,
             const float* __restrict__ b1, const float* __restrict__ g1, const float* __restrict__ be1,
             const float* __restrict__ b2, const float* __restrict__ g2, const float* __restrict__ be2,
             const float* __restrict__ b3,
             int Npts, int ntiles)
{
    extern __shared__ char smem_raw[];
    __half* sbufh = (__half*)smem_raw;              // 16*PITCHH halves
    __half* zsh   = sbufh + MT * PITCHH;            // 16*ZPH halves
    float* sb1   = (float*)(zsh + MT * ZPH);
    float* sg1   = sb1 + HDIM;
    float* sbe1  = sg1 + HDIM;
    float* sb2   = sbe1 + HDIM;
    float* sg2   = sb2 + HDIM;
    float* sbe2  = sg2 + HDIM;
    float* sb3   = sbe2 + HDIM;                     // 128
    float* red_s = sb3 + DOUT;                      // 64
    float* red_q = red_s + 64;                      // 64
    float* s_m   = red_q + 64;                      // 16
    float* s_r   = s_m + MT;                        // 16
    int*   ssg   = (int*)(s_r + MT);                // 16
    float* fbuf  = (float*)smem_raw;                // layer-3 C view, pitch FPITCH (16*132*4 = sbufh size)

    const int tid = threadIdx.x;
    const int warp = tid >> 5, lane = tid & 31;
    const int g = lane >> 2, tg = lane & 3;
    const int nq = warp;                            // n-slice index (4 warps)
    const int n0 = 64 * nq;                         // 64-col slice for H=256 layers
    const int n3 = 32 * nq;                         // 32-col slice for DOUT=128

    // LDSM lane addressing (16 rows, one m-tile)
    const int lrow = (lane & 7) + ((lane >> 3) & 1) * 8;
    const int lcol = (lane >> 4) * 8;
    const unsigned lds_z0 = smem_u32(zsh) + (unsigned)((lrow * ZPH + lcol) * 2);
    const unsigned lds_a0 = smem_u32(sbufh) + (unsigned)((lrow * PITCHH + lcol) * 2);

    // ---- one-time param load (128 threads -> 2 rounds of 256) ----
    #pragma unroll
    for (int r = 0; r < 2; r++) {
        int i = tid + 128 * r;
        sb1[i] = b1[i]; sg1[i] = g1[i]; sbe1[i] = be1[i];
        sb2[i] = b2[i]; sg2[i] = g2[i]; sbe2[i] = be2[i];
    }
    if (tid < DOUT) sb3[tid] = b3[tid];
    __syncthreads();

    uint2 bw0[4], bw1[4];   // B-fragment pipeline registers
    float4 acc[8];

    for (int tile = blockIdx.x; tile < ntiles; tile += gridDim.x) {
        const int p0 = tile * MT;
        const int npts = min(MT, Npts - p0);

        // layer-1 weights (L1-cache resident) — low half now, high half after
        #pragma unroll
        for (int t = 0; t < 4; t++)
            bw0[t] = d_W1h[(n0 + 8 * t + g) * 4 + tg];
        #pragma unroll
        for (int t = 0; t < 4; t++)
            bw1[t] = d_W1h[(n0 + 32 + 8 * t + g) * 4 + tg];

        // ---- z tile + seg ids (16 pts x 4 float4 = 64 threads) ----
        {
            int pi = tid >> 2, ci = tid & 3;
            if (pi < MT) {
                const float4* z4 = (const float4*)(z + (long long)p0 * DIN);
                float4 v = make_float4(0.f, 0.f, 0.f, 0.f);
                if (pi < npts) v = z4[pi * 4 + ci];
                *(uint2*)(zsh + pi * ZPH + 4 * ci) = make_uint2(h2u(v.x, v.y), h2u(v.z, v.w));
            }
            if (tid < MT) ssg[tid] = (tid < npts) ? d_seg[p0 + tid] : 0;
        }
        __syncthreads();

        // ================= Layer 1: [16x16] @ [16x256] =================
        #pragma unroll
        for (int t = 0; t < 8; t++) acc[t] = make_float4(0.f, 0.f, 0.f, 0.f);
        {
            unsigned a[4];
            ldsm_x4(a[0], a[1], a[2], a[3], lds_z0);
            #pragma unroll
            for (int t = 0; t < 4; t++)
                mma_f16(acc[t], a[0], a[1], a[2], a[3], bw0[t].x, bw0[t].y);
            #pragma unroll
            for (int t = 0; t < 4; t++)
                mma_f16(acc[4 + t], a[0], a[1], a[2], a[3], bw1[t].x, bw1[t].y);
        }
        // preload layer-2 chunk0 low half (latency hidden under LN1)
        #pragma unroll
        for (int t = 0; t < 4; t++)
            bw0[t] = d_W2h[(n0 + 8 * t + g) * 4 + tg];

        ln_relu_reg(acc, sbufh, sb1, sg1, sbe1, red_s, red_q, s_m, s_r, g, tg, n0, nq, tid);

        // ================= Layer 2: [16x256] @ [256x256], 16 k16 chunks =================
        #pragma unroll
        for (int t = 0; t < 8; t++) acc[t] = make_float4(0.f, 0.f, 0.f, 0.f);

        #pragma unroll 1
        for (int c = 0; c < 16; c++) {
            // prefetch high half of chunk c
            #pragma unroll
            for (int t = 0; t < 4; t++)
                bw1[t] = d_W2h[(c * HDIM + n0 + 32 + 8 * t + g) * 4 + tg];
            const unsigned koff = (unsigned)(32 * c);
            unsigned a[4];
            ldsm_x4(a[0], a[1], a[2], a[3], lds_a0 + koff);
            #pragma unroll
            for (int t = 0; t < 4; t++)
                mma_f16(acc[t], a[0], a[1], a[2], a[3], bw0[t].x, bw0[t].y);
            if (c + 1 < 16) {
                #pragma unroll
                for (int t = 0; t < 4; t++)
                    bw0[t] = d_W2h[((c + 1) * HDIM + n0 + 8 * t + g) * 4 + tg];
            }
            #pragma unroll
            for (int t = 0; t < 4; t++)
                mma_f16(acc[4 + t], a[0], a[1], a[2], a[3], bw1[t].x, bw1[t].y);
        }
        // preload layer-3 chunk0 (hidden under LN2)
        #pragma unroll
        for (int t = 0; t < 4; t++)
            bw0[t] = d_W3h[(n3 + 8 * t + g) * 4 + tg];

        ln_relu_reg(acc, sbufh, sb2, sg2, sbe2, red_s, red_q, s_m, s_r, g, tg, n0, nq, tid);

        // ================= Layer 3: [16x256] @ [256x128] =================
        {
            float4 acc3[4];
            #pragma unroll
            for (int t = 0; t < 4; t++) acc3[t] = make_float4(0.f, 0.f, 0.f, 0.f);

            #pragma unroll 1
            for (int c = 0; c < 16; c += 2) {
                #pragma unroll
                for (int t = 0; t < 4; t++)
                    bw1[t] = d_W3h[((c + 1) * DOUT + n3 + 8 * t + g) * 4 + tg];
                {
                    const unsigned koff = (unsigned)(32 * c);
                    unsigned a[4];
                    ldsm_x4(a[0], a[1], a[2], a[3], lds_a0 + koff);
                    #pragma unroll
                    for (int t = 0; t < 4; t++)
                        mma_f16(acc3[t], a[0], a[1], a[2], a[3], bw0[t].x, bw0[t].y);
                }
                if (c + 2 < 16) {
                    #pragma unroll
                    for (int t = 0; t < 4; t++)
                        bw0[t] = d_W3h[((c + 2) * DOUT + n3 + 8 * t + g) * 4 + tg];
                }
                {
                    const unsigned koff = (unsigned)(32 * (c + 1));
                    unsigned a[4];
                    ldsm_x4(a[0], a[1], a[2], a[3], lds_a0 + koff);
                    #pragma unroll
                    for (int t = 0; t < 4; t++)
                        mma_f16(acc3[t], a[0], a[1], a[2], a[3], bw1[t].x, bw1[t].y);
                }
            }
            __syncthreads();   // all sbuf A reads done before overwriting with C3 (float view)
            #pragma unroll
            for (int t = 0; t < 4; t++) {
                float* cr = fbuf + g * FPITCH + n3 + 8 * t + 2 * tg;
                cr[0] = acc3[t].x; cr[1] = acc3[t].y;
                cr[8 * FPITCH] = acc3[t].z; cr[8 * FPITCH + 1] = acc3[t].w;
            }
        }
        __syncthreads();

        // ================= epilogue: bias + run-length segment accumulate =================
        {
            const int f = tid;                       // one feature per thread (128 = DOUT)
            const float bf = sb3[f];
            int cur = ssg[0];
            float run = 0.f;
            for (int p = 0; p < npts; p++) {
                float phi = fbuf[p * FPITCH + f] + bf;
                int sp = ssg[p];
                if (sp != cur) {
                    atomicAdd(&d_sums[cur * DOUT + f], run);
                    run = 0.f;
                    cur = sp;
                }
                run += phi;
            }
            atomicAdd(&d_sums[cur * DOUT + f], run);
        }
        __syncthreads();   // fbuf/ssg reads done before next iteration overwrites
    }
}

__global__ void finalize_means(int Bn) {
    int i = blockIdx.x * blockDim.x + threadIdx.x;
    if (i < Bn * DOUT) {
        int b = i >> 7;
        float cnt = (float)(d_offs[b + 1] - d_offs[b]);
        d_emb[i] = d_sums[i] / cnt;
    }
}

__global__ void broadcast_out(float4* __restrict__ out, long long total4) {
    long long i = (long long)blockIdx.x * blockDim.x + threadIdx.x;
    if (i < total4) {
        long long p = i >> 5;
        int c = (int)(i & 31);
        const float4* emb4 = reinterpret_cast<const float4*>(d_emb);
        out[i] = emb4[(long long)d_seg[p] * 32 + c];
    }
}

extern "C" void kernel_launch(void* const* d_in, const int* in_sizes, int n_in,
                              void* d_out, int out_size) {
    const float* z   = (const float*)d_in[0];
    const float* W1  = (const float*)d_in[1];
    const float* b1  = (const float*)d_in[2];
    const float* g1  = (const float*)d_in[3];
    const float* be1 = (const float*)d_in[4];
    const float* W2  = (const float*)d_in[5];
    const float* b2  = (const float*)d_in[6];
    const float* g2  = (const float*)d_in[7];
    const float* be2 = (const float*)d_in[8];
    const float* W3  = (const float*)d_in[9];
    const float* b3  = (const float*)d_in[10];
    const void*  np  = d_in[11];

    const int Bn = in_sizes[11];
    const int N  = in_sizes[0] / DIN;

    static const size_t SMEM_BYTES =
        (MT * PITCHH + MT * ZPH) * sizeof(__half)
        + (6 * HDIM + DOUT + 64 + 64 + 2 * MT) * sizeof(float)
        + MT * sizeof(int);
    cudaFuncSetAttribute(mlp_mma, cudaFuncAttributeMaxDynamicSharedMemorySize,
                         (int)SMEM_BYTES);

    int dev = 0, nsm = 148;
    cudaGetDevice(&dev);
    cudaDeviceGetAttribute(&nsm, cudaDevAttrMultiProcessorCount, dev);

    // mlp_mma kept as the 4th launch (ncu capture slot)
    scan_offsets<<<1, 256>>>(np, Bn);
    cvt_weights<<<64, 256>>>(W1, W2, W3);
    fill_seg_zero<<<Bn + (Bn * DOUT + 127) / 128, 128>>>(Bn);

    const int ntiles = (N + MT - 1) / MT;
    int grid = 6 * nsm;
    if (grid > ntiles) grid = ntiles;
    mlp_mma<<<grid, TPB, SMEM_BYTES>>>(z, b1, g1, be1, b2, g2, be2, b3, N, ntiles);

    finalize_means<<<(Bn * DOUT + 255) / 256, 256>>>(Bn);

    const long long total4 = (long long)N * (DOUT / 4);
    broadcast_out<<<(int)((total4 + 255) / 256), 256>>>((float4*)d_out, total4);
}

// round 14
// speedup vs baseline: 1.0105x; 1.0105x over previous
#include <cuda_runtime.h>
#include <cuda_fp16.h>
#include <cstdint>

#define TPB    256
#define MT     64          // points per tile
#define HDIM   256
#define DIN    16
#define DOUT   128
#define PITCHH 264         // sbuf pitch in halves; row stride 528B -> LDSM conflict-free
#define FPITCH 132         // float view pitch for layer-3 C / epilogue
#define ZPH    24          // z tile pitch in halves
#define BMAX   4096
#define NMAX   1100000

// ---------------- device scratch (no allocations allowed) ----------------
__device__ long long d_offs[BMAX + 1];
__device__ int       d_seg[NMAX];
__device__ float     d_sums[BMAX * DOUT];
__device__ float     d_emb[BMAX * DOUT];
// lane-major packed fp16 weights (uint4 pairs per lane):
//  W2: idx = c*512 + nq*128 + h*64 + lane*2        (c<16, h<2)  -> 8192 uint4
//  W3: idx = c*256 + nq*64 + lane*2                (c<16)       -> 4096 uint4
//  W1: idx = nq*128 + h*64 + lane*2                             -> 512 uint4
__device__ __align__(16) uint4 d_W2r4[8192];
__device__ __align__(16) uint4 d_W3r4[4096];
__device__ __align__(16) uint4 d_W1r4[512];

// ---------------- helpers ----------------
__device__ __forceinline__ unsigned h2u(float a, float b) {
    __half2 h = __floats2half2_rn(a, b);
    return *reinterpret_cast<unsigned*>(&h);
}

__device__ __forceinline__ void mma_f16(float4& d,
                                        unsigned a0, unsigned a1, unsigned a2, unsigned a3,
                                        unsigned b0, unsigned b1) {
    asm volatile(
        "mma.sync.aligned.m16n8k16.row.col.f32.f16.f16.f32 "
        "{%0,%1,%2,%3}, {%4,%5,%6,%7}, {%8,%9}, {%0,%1,%2,%3};"
        : "+f"(d.x), "+f"(d.y), "+f"(d.z), "+f"(d.w)
        : "r"(a0), "r"(a1), "r"(a2), "r"(a3), "r"(b0), "r"(b1));
}

__device__ __forceinline__ void ldsm_x4(unsigned& r0, unsigned& r1, unsigned& r2, unsigned& r3,
                                        unsigned addr) {
    asm volatile("ldmatrix.sync.aligned.m8n8.x4.shared.b16 {%0,%1,%2,%3}, [%4];"
                 : "=r"(r0), "=r"(r1), "=r"(r2), "=r"(r3) : "r"(addr));
}

__device__ __forceinline__ unsigned smem_u32(const void* p) {
    return (unsigned)__cvta_generic_to_shared(p);
}

// load 4 B-fragments (uint2 each) from 2 consecutive uint4
__device__ __forceinline__ void ldw4(uint2* bw, const uint4* p) {
    uint4 a = p[0], b = p[1];
    bw[0] = make_uint2(a.x, a.y); bw[1] = make_uint2(a.z, a.w);
    bw[2] = make_uint2(b.x, b.y); bw[3] = make_uint2(b.z, b.w);
}

__device__ __forceinline__ long long get_count(const void* np, int i, int is64) {
    if (is64) return ((const long long*)np)[i];
    return (long long)((const int*)np)[i];
}

// ---------------- small setup kernels ----------------
__global__ void scan_offsets(const void* __restrict__ np, int Bn) {
    __shared__ long long part[256];
    __shared__ int s_is64;
    if (threadIdx.x == 0) {
        const int* p32 = (const int*)np;
        int is64 = 1;
        for (int i = 1; i < 7 && i < 2 * Bn; i += 2)
            if (p32[i] != 0) is64 = 0;
        s_is64 = is64;
    }
    __syncthreads();
    const int is64 = s_is64;
    const int chunk = (Bn + 255) / 256;
    const int c0 = threadIdx.x * chunk;
    long long s = 0;
    for (int i = 0; i < chunk; i++) {
        int idx = c0 + i;
        if (idx < Bn) s += get_count(np, idx, is64);
    }
    part[threadIdx.x] = s;
    __syncthreads();
    if (threadIdx.x == 0) {
        long long r = 0;
        for (int i = 0; i < 256; i++) { long long t = part[i]; part[i] = r; r += t; }
    }
    __syncthreads();
    long long base = part[threadIdx.x];
    for (int i = 0; i < chunk; i++) {
        int idx = c0 + i;
        if (idx < Bn) {
            d_offs[idx] = base;
            base += get_count(np, idx, is64);
            if (idx == Bn - 1) d_offs[Bn] = base;
        }
    }
}

// fused: blocks [0,Bn) fill seg ids; blocks [Bn, ...) zero d_sums
__global__ void fill_seg_zero(int Bn) {
    int b = blockIdx.x;
    if (b < Bn) {
        long long lo = d_offs[b], hi = d_offs[b + 1];
        for (long long i = lo + threadIdx.x; i < hi; i += blockDim.x)
            d_seg[i] = b;
    } else {
        int i = (b - Bn) * blockDim.x + threadIdx.x;
        if (i < Bn * DOUT) d_sums[i] = 0.f;
    }
}

// pack weights into lane-major uint4 layout
__global__ void cvt_weights(const float* __restrict__ W1,
                            const float* __restrict__ W2,
                            const float* __restrict__ W3) {
    int i = blockIdx.x * 256 + threadIdx.x;   // 32 blocks x 256 = 8192 threads
    // W2r4 [8192]
    if (i < 8192) {
        int pair = i & 1, lane = (i >> 1) & 31, h = (i >> 6) & 1, nq = (i >> 7) & 3, c = i >> 9;
        int g = lane >> 2, tg = lane & 3;
        int k = 16 * c + 2 * tg;
        uint4 out;
        {
            int t = 2 * pair;
            int n = 64 * nq + 32 * h + 8 * t + g;
            out.x = h2u(W2[k * HDIM + n],       W2[(k + 1) * HDIM + n]);
            out.y = h2u(W2[(k + 8) * HDIM + n], W2[(k + 9) * HDIM + n]);
        }
        {
            int t = 2 * pair + 1;
            int n = 64 * nq + 32 * h + 8 * t + g;
            out.z = h2u(W2[k * HDIM + n],       W2[(k + 1) * HDIM + n]);
            out.w = h2u(W2[(k + 8) * HDIM + n], W2[(k + 9) * HDIM + n]);
        }
        d_W2r4[i] = out;
    }
    // W3r4 [4096]
    if (i < 4096) {
        int pair = i & 1, lane = (i >> 1) & 31, nq = (i >> 6) & 3, c = i >> 8;
        int g = lane >> 2, tg = lane & 3;
        int k = 16 * c + 2 * tg;
        uint4 out;
        {
            int t = 2 * pair;
            int n = 32 * nq + 8 * t + g;
            out.x = h2u(W3[k * DOUT + n],       W3[(k + 1) * DOUT + n]);
            out.y = h2u(W3[(k + 8) * DOUT + n], W3[(k + 9) * DOUT + n]);
        }
        {
            int t = 2 * pair + 1;
            int n = 32 * nq + 8 * t + g;
            out.z = h2u(W3[k * DOUT + n],       W3[(k + 1) * DOUT + n]);
            out.w = h2u(W3[(k + 8) * DOUT + n], W3[(k + 9) * DOUT + n]);
        }
        d_W3r4[i] = out;
    }
    // W1r4 [512]
    if (i < 512) {
        int pair = i & 1, lane = (i >> 1) & 31, h = (i >> 6) & 1, nq = (i >> 7) & 3;
        int g = lane >> 2, tg = lane & 3;
        int k = 2 * tg;
        uint4 out;
        {
            int t = 2 * pair;
            int n = 64 * nq + 32 * h + 8 * t + g;
            out.x = h2u(W1[k * HDIM + n],       W1[(k + 1) * HDIM + n]);
            out.y = h2u(W1[(k + 8) * HDIM + n], W1[(k + 9) * HDIM + n]);
        }
        {
            int t = 2 * pair + 1;
            int n = 64 * nq + 32 * h + 8 * t + g;
            out.z = h2u(W1[k * HDIM + n],       W1[(k + 1) * HDIM + n]);
            out.w = h2u(W1[(k + 8) * HDIM + n], W1[(k + 9) * HDIM + n]);
        }
        d_W1r4[i] = out;
    }
}

// ---------------- in-register LN + ReLU -> fp16 smem (2m x 8n warp layout) ----------------
// 2 barriers: partial write -> sync -> every thread reduces its rows -> store -> sync
__device__ __forceinline__ void ln_relu_reg(
    float4 (&acc)[2][8], __half* __restrict__ sbufh,
    const float* __restrict__ bi, const float* __restrict__ ga, const float* __restrict__ be,
    float* __restrict__ red_s, float* __restrict__ red_q,
    int g, int tg, int n0, int rb, int nq)
{
    #pragma unroll
    for (int t = 0; t < 8; t++) {
        const float2 bb = *(const float2*)(bi + n0 + 8 * t + 2 * tg);
        #pragma unroll
        for (int m = 0; m < 2; m++) {
            acc[m][t].x += bb.x; acc[m][t].y += bb.y;
            acc[m][t].z += bb.x; acc[m][t].w += bb.y;
        }
    }
    float s[2][2], q[2][2];
    #pragma unroll
    for (int m = 0; m < 2; m++) {
        float sl = 0.f, ql = 0.f, sh = 0.f, qh = 0.f;
        #pragma unroll
        for (int t = 0; t < 8; t++) {
            float4 v = acc[m][t];
            sl += v.x + v.y;  ql += v.x * v.x + v.y * v.y;
            sh += v.z + v.w;  qh += v.z * v.z + v.w * v.w;
        }
        s[m][0] = sl; q[m][0] = ql; s[m][1] = sh; q[m][1] = qh;
    }
    #pragma unroll
    for (int o = 1; o <= 2; o <<= 1) {
        #pragma unroll
        for (int m = 0; m < 2; m++) {
            #pragma unroll
            for (int h = 0; h < 2; h++) {
                s[m][h] += __shfl_xor_sync(0xffffffffu, s[m][h], o);
                q[m][h] += __shfl_xor_sync(0xffffffffu, q[m][h], o);
            }
        }
    }
    if (tg == 0) {
        #pragma unroll
        for (int m = 0; m < 2; m++) {
            red_s[(rb + 16 * m + g) * 4 + nq]     = s[m][0];
            red_q[(rb + 16 * m + g) * 4 + nq]     = q[m][0];
            red_s[(rb + 16 * m + g + 8) * 4 + nq] = s[m][1];
            red_q[(rb + 16 * m + g + 8) * 4 + nq] = q[m][1];
        }
    }
    __syncthreads();
    #pragma unroll
    for (int m = 0; m < 2; m++) {
        const int r0 = rb + 16 * m + g;
        float ssl = 0.f, qql = 0.f, ssh = 0.f, qqh = 0.f;
        #pragma unroll
        for (int w = 0; w < 4; w++) {
            ssl += red_s[r0 * 4 + w];       qql += red_q[r0 * 4 + w];
            ssh += red_s[(r0 + 8) * 4 + w]; qqh += red_q[(r0 + 8) * 4 + w];
        }
        const float ml = ssl * (1.f / 256.f);
        const float rl = rsqrtf(qql * (1.f / 256.f) - ml * ml + 1e-5f);
        const float mh = ssh * (1.f / 256.f);
        const float rh = rsqrtf(qqh * (1.f / 256.f) - mh * mh + 1e-5f);
        #pragma unroll
        for (int t = 0; t < 8; t++) {
            const int col = n0 + 8 * t + 2 * tg;
            const float2 gg = *(const float2*)(ga + col);
            const float2 ee = *(const float2*)(be + col);
            unsigned lo = h2u(fmaxf((acc[m][t].x - ml) * rl * gg.x + ee.x, 0.f),
                              fmaxf((acc[m][t].y - ml) * rl * gg.y + ee.y, 0.f));
            unsigned hi = h2u(fmaxf((acc[m][t].z - mh) * rh * gg.x + ee.x, 0.f),
                              fmaxf((acc[m][t].w - mh) * rh * gg.y + ee.y, 0.f));
            *(unsigned*)(sbufh + (r0) * PITCHH + col)     = lo;
            *(unsigned*)(sbufh + (r0 + 8) * PITCHH + col) = hi;
        }
    }
    __syncthreads();
}

// ---------------- main fused persistent kernel (2 CTAs/SM, 64-pt tiles) ----------------
__global__ __launch_bounds__(TPB, 2)
void mlp_mma(const float* __restrict__ z,
             const float* __restrict__ b1, const float* __restrict__ g1, const float* __restrict__ be1,
             const float* __restrict__ b2, const float* __restrict__ g2, const float* __restrict__ be2,
             const float* __restrict__ b3,
             int Npts, int ntiles)
{
    extern __shared__ char smem_raw[];
    __half* sbufh = (__half*)smem_raw;              // 64*PITCHH halves
    __half* zsh   = sbufh + MT * PITCHH;            // 64*ZPH halves
    float* sb1   = (float*)(zsh + MT * ZPH);
    float* sg1   = sb1 + HDIM;
    float* sbe1  = sg1 + HDIM;
    float* sb2   = sbe1 + HDIM;
    float* sg2   = sb2 + HDIM;
    float* sbe2  = sg2 + HDIM;
    float* sb3   = sbe2 + HDIM;                     // 128
    float* red_s = sb3 + DOUT;                      // 256
    float* red_q = red_s + 256;                     // 256
    int*   ssg   = (int*)(red_q + 256);             // 64
    float* fbuf  = (float*)smem_raw;                // layer-3 C view, pitch FPITCH

    const int tid = threadIdx.x;
    const int warp = tid >> 5, lane = tid & 31;
    const int g = lane >> 2, tg = lane & 3;
    const int nq = warp & 3, mh = warp >> 2;
    const int rb = 32 * mh;                         // row base (32-row half)
    const int n0 = 64 * nq;                         // 64-col slice for H=256 layers
    const int n3 = 32 * nq;                         // 32-col slice for DOUT=128

    // lane-major weight base pointers
    const uint4* wbase1 = d_W1r4 + (nq * 128 + lane * 2);
    const uint4* wbase2 = d_W2r4 + (nq * 128 + lane * 2);
    const uint4* wbase3 = d_W3r4 + (nq * 64 + lane * 2);

    // LDSM lane addressing (rows 0..31 within half, 2 m-tiles)
    const int lrow = (lane & 7) + ((lane >> 3) & 1) * 8;
    const int lcol = (lane >> 4) * 8;
    const unsigned zbase = smem_u32(zsh);
    const unsigned lds_z0 = zbase + (unsigned)(((rb + lrow) * ZPH + lcol) * 2);
    const unsigned lds_z1 = zbase + (unsigned)(((rb + 16 + lrow) * ZPH + lcol) * 2);
    const unsigned hbase = smem_u32(sbufh);
    const unsigned lds_a0 = hbase + (unsigned)(((rb + lrow) * PITCHH + lcol) * 2);
    const unsigned lds_a1 = hbase + (unsigned)(((rb + 16 + lrow) * PITCHH + lcol) * 2);

    // ---- one-time param load ----
    sb1[tid] = b1[tid]; sg1[tid] = g1[tid]; sbe1[tid] = be1[tid];
    sb2[tid] = b2[tid]; sg2[tid] = g2[tid]; sbe2[tid] = be2[tid];
    if (tid < DOUT) sb3[tid] = b3[tid];
    __syncthreads();

    uint2 bw0[4], bw1[4];   // B-fragment pipeline registers
    float4 acc[2][8];

    for (int tile = blockIdx.x; tile < ntiles; tile += gridDim.x) {
        const int p0 = tile * MT;
        const int npts = min(MT, Npts - p0);

        // layer-1 weights (L1-resident): both halves
        uint2 w1l[4], w1h[4];
        ldw4(w1l, wbase1);
        ldw4(w1h, wbase1 + 64);

        // ---- z tile + seg ids ----
        {
            const float4* z4 = (const float4*)(z + (long long)p0 * DIN);
            int pi = tid >> 2, ci = tid & 3;
            float4 v = make_float4(0.f, 0.f, 0.f, 0.f);
            if (pi < npts) v = z4[pi * 4 + ci];
            *(uint2*)(zsh + pi * ZPH + 4 * ci) = make_uint2(h2u(v.x, v.y), h2u(v.z, v.w));
            if (tid < MT) ssg[tid] = (tid < npts) ? d_seg[p0 + tid] : 0;
        }
        __syncthreads();

        // ================= Layer 1: [64x16] @ [16x256], single k16 chunk =================
        #pragma unroll
        for (int m = 0; m < 2; m++)
            #pragma unroll
            for (int t = 0; t < 8; t++) acc[m][t] = make_float4(0.f, 0.f, 0.f, 0.f);
        {
            unsigned a[2][4];
            ldsm_x4(a[0][0], a[0][1], a[0][2], a[0][3], lds_z0);
            ldsm_x4(a[1][0], a[1][1], a[1][2], a[1][3], lds_z1);
            #pragma unroll
            for (int t = 0; t < 4; t++)
                #pragma unroll
                for (int m = 0; m < 2; m++)
                    mma_f16(acc[m][t], a[m][0], a[m][1], a[m][2], a[m][3],
                            w1l[t].x, w1l[t].y);
            #pragma unroll
            for (int t = 0; t < 4; t++)
                #pragma unroll
                for (int m = 0; m < 2; m++)
                    mma_f16(acc[m][4 + t], a[m][0], a[m][1], a[m][2], a[m][3],
                            w1h[t].x, w1h[t].y);
        }
        // preload layer-2 chunk0 low half (latency hidden under LN1)
        ldw4(bw0, wbase2);

        ln_relu_reg(acc, sbufh, sb1, sg1, sbe1, red_s, red_q, g, tg, n0, rb, nq);

        // ================= Layer 2: [64x256] @ [256x256], 16 k16 chunks =================
        #pragma unroll
        for (int m = 0; m < 2; m++)
            #pragma unroll
            for (int t = 0; t < 8; t++) acc[m][t] = make_float4(0.f, 0.f, 0.f, 0.f);

        #pragma unroll 1
        for (int c = 0; c < 16; c++) {
            // prefetch high half of chunk c
            ldw4(bw1, wbase2 + c * 512 + 64);
            unsigned a[2][4];
            ldsm_x4(a[0][0], a[0][1], a[0][2], a[0][3], lds_a0 + (unsigned)(32 * c));
            ldsm_x4(a[1][0], a[1][1], a[1][2], a[1][3], lds_a1 + (unsigned)(32 * c));
            // compute low half (t=0..3) with bw0
            #pragma unroll
            for (int t = 0; t < 4; t++)
                #pragma unroll
                for (int m = 0; m < 2; m++)
                    mma_f16(acc[m][t], a[m][0], a[m][1], a[m][2], a[m][3],
                            bw0[t].x, bw0[t].y);
            // prefetch low half of chunk c+1
            if (c + 1 < 16) ldw4(bw0, wbase2 + (c + 1) * 512);
            // compute high half (t=4..7) with bw1
            #pragma unroll
            for (int t = 0; t < 4; t++)
                #pragma unroll
                for (int m = 0; m < 2; m++)
                    mma_f16(acc[m][4 + t], a[m][0], a[m][1], a[m][2], a[m][3],
                            bw1[t].x, bw1[t].y);
        }
        // preload layer-3 chunk0 (hidden under LN2)
        ldw4(bw0, wbase3);

        ln_relu_reg(acc, sbufh, sb2, sg2, sbe2, red_s, red_q, g, tg, n0, rb, nq);

        // ================= Layer 3: [64x256] @ [256x128] =================
        {
            float4 acc3[2][4];
            #pragma unroll
            for (int m = 0; m < 2; m++)
                #pragma unroll
                for (int t = 0; t < 4; t++) acc3[m][t] = make_float4(0.f, 0.f, 0.f, 0.f);

            #pragma unroll 1
            for (int c = 0; c < 16; c += 2) {
                ldw4(bw1, wbase3 + (c + 1) * 256);
                {
                    unsigned a[2][4];
                    ldsm_x4(a[0][0], a[0][1], a[0][2], a[0][3], lds_a0 + (unsigned)(32 * c));
                    ldsm_x4(a[1][0], a[1][1], a[1][2], a[1][3], lds_a1 + (unsigned)(32 * c));
                    #pragma unroll
                    for (int t = 0; t < 4; t++)
                        #pragma unroll
                        for (int m = 0; m < 2; m++)
                            mma_f16(acc3[m][t], a[m][0], a[m][1], a[m][2], a[m][3],
                                    bw0[t].x, bw0[t].y);
                }
                if (c + 2 < 16) ldw4(bw0, wbase3 + (c + 2) * 256);
                {
                    unsigned a[2][4];
                    ldsm_x4(a[0][0], a[0][1], a[0][2], a[0][3], lds_a0 + (unsigned)(32 * (c + 1)));
                    ldsm_x4(a[1][0], a[1][1], a[1][2], a[1][3], lds_a1 + (unsigned)(32 * (c + 1)));
                    #pragma unroll
                    for (int t = 0; t < 4; t++)
                        #pragma unroll
                        for (int m = 0; m < 2; m++)
                            mma_f16(acc3[m][t], a[m][0], a[m][1], a[m][2], a[m][3],
                                    bw1[t].x, bw1[t].y);
                }
            }
            __syncthreads();   // all sbuf A reads done before overwriting with C3 (float view)
            #pragma unroll
            for (int m = 0; m < 2; m++)
                #pragma unroll
                for (int t = 0; t < 4; t++) {
                    float* cr = fbuf + (rb + 16 * m + g) * FPITCH + n3 + 8 * t + 2 * tg;
                    cr[0] = acc3[m][t].x; cr[1] = acc3[m][t].y;
                    cr[8 * FPITCH] = acc3[m][t].z; cr[8 * FPITCH + 1] = acc3[m][t].w;
                }
        }
        __syncthreads();

        // ================= epilogue: bias + run-length segment accumulate =================
        {
            const int f = tid & (DOUT - 1);
            const int half = tid >> 7;
            const int ps = half * 32;
            const int pe = min(ps + 32, npts);
            if (ps < pe) {
                const float bf = sb3[f];
                int cur = ssg[ps];
                float run = 0.f;
                for (int p = ps; p < pe; p++) {
                    float phi = fbuf[p * FPITCH + f] + bf;
                    int sp = ssg[p];
                    if (sp != cur) {
                        atomicAdd(&d_sums[cur * DOUT + f], run);
                        run = 0.f;
                        cur = sp;
                    }
                    run += phi;
                }
                atomicAdd(&d_sums[cur * DOUT + f], run);
            }
        }
        __syncthreads();   // fbuf/ssg reads done before next iteration overwrites
    }
}

__global__ void finalize_means(int Bn) {
    int i = blockIdx.x * blockDim.x + threadIdx.x;
    if (i < Bn * DOUT) {
        int b = i >> 7;
        float cnt = (float)(d_offs[b + 1] - d_offs[b]);
        d_emb[i] = d_sums[i] / cnt;
    }
}

__global__ void broadcast_out(float4* __restrict__ out, long long total4) {
    long long i = (long long)blockIdx.x * blockDim.x + threadIdx.x;
    if (i < total4) {
        long long p = i >> 5;
        int c = (int)(i & 31);
        const float4* emb4 = reinterpret_cast<const float4*>(d_emb);
        out[i] = emb4[(long long)d_seg[p] * 32 + c];
    }
}

extern "C" void kernel_launch(void* const* d_in, const int* in_sizes, int n_in,
                              void* d_out, int out_size) {
    const float* z   = (const float*)d_in[0];
    const float* W1  = (const float*)d_in[1];
    const float* b1  = (const float*)d_in[2];
    const float* g1  = (const float*)d_in[3];
    const float* be1 = (const float*)d_in[4];
    const float* W2  = (const float*)d_in[5];
    const float* b2  = (const float*)d_in[6];
    const float* g2  = (const float*)d_in[7];
    const float* be2 = (const float*)d_in[8];
    const float* W3  = (const float*)d_in[9];
    const float* b3  = (const float*)d_in[10];
    const void*  np  = d_in[11];

    const int Bn = in_sizes[11];
    const int N  = in_sizes[0] / DIN;

    static const size_t SMEM_BYTES =
        (MT * PITCHH + MT * ZPH) * sizeof(__half)
        + (6 * HDIM + DOUT + 256 + 256) * sizeof(float)
        + MT * sizeof(int);
    cudaFuncSetAttribute(mlp_mma, cudaFuncAttributeMaxDynamicSharedMemorySize,
                         (int)SMEM_BYTES);

    int dev = 0, nsm = 148;
    cudaGetDevice(&dev);
    cudaDeviceGetAttribute(&nsm, cudaDevAttrMultiProcessorCount, dev);

    // mlp_mma kept as the 4th launch (ncu capture slot)
    scan_offsets<<<1, 256>>>(np, Bn);
    cvt_weights<<<32, 256>>>(W1, W2, W3);
    fill_seg_zero<<<Bn + (Bn * DOUT + 127) / 128, 128>>>(Bn);

    const int ntiles = (N + MT - 1) / MT;
    int grid = 2 * nsm;
    if (grid > ntiles) grid = ntiles;
    mlp_mma<<<grid, TPB, SMEM_BYTES>>>(z, b1, g1, be1, b2, g2, be2, b3, N, ntiles);

    finalize_means<<<(Bn * DOUT + 255) / 256, 256>>>(Bn);

    const long long total4 = (long long)N * (DOUT / 4);
    broadcast_out<<<(int)((total4 + 255) / 256), 256>>>((float4*)d_out, total4);
}

// round 15
// speedup vs baseline: 1.0249x; 1.0143x over previous
#include <cuda_runtime.h>
#include <cuda_fp16.h>
#include <cstdint>

#define TPB    256
#define MT     64          // points per tile
#define HDIM   256
#define DIN    16
#define DOUT   128
#define PITCHH 264         // sbuf pitch in halves; row stride 528B -> LDSM conflict-free
#define FPITCH 132         // float view pitch for layer-3 C / epilogue
#define ZPH    24          // z tile pitch in halves
#define BMAX   4096
#define NMAX   1100000

// ---------------- device scratch (no allocations allowed) ----------------
__device__ long long d_offs[BMAX + 1];
__device__ int       d_seg[NMAX];
__device__ float     d_sums[BMAX * DOUT];
__device__ float     d_emb[BMAX * DOUT];
// lane-major packed fp16 weights (uint4 pairs per lane):
//  W2: idx = c*512 + nq*128 + h*64 + lane*2        (c<16, h<2)  -> 8192 uint4
//  W3: idx = c*256 + nq*64 + lane*2                (c<16)       -> 4096 uint4
//  W1: idx = nq*128 + h*64 + lane*2                             -> 512 uint4
__device__ __align__(16) uint4 d_W2r4[8192];
__device__ __align__(16) uint4 d_W3r4[4096];
__device__ __align__(16) uint4 d_W1r4[512];

// ---------------- helpers ----------------
__device__ __forceinline__ unsigned h2u(float a, float b) {
    __half2 h = __floats2half2_rn(a, b);
    return *reinterpret_cast<unsigned*>(&h);
}

__device__ __forceinline__ void mma_f16(float4& d,
                                        unsigned a0, unsigned a1, unsigned a2, unsigned a3,
                                        unsigned b0, unsigned b1) {
    asm volatile(
        "mma.sync.aligned.m16n8k16.row.col.f32.f16.f16.f32 "
        "{%0,%1,%2,%3}, {%4,%5,%6,%7}, {%8,%9}, {%0,%1,%2,%3};"
        : "+f"(d.x), "+f"(d.y), "+f"(d.z), "+f"(d.w)
        : "r"(a0), "r"(a1), "r"(a2), "r"(a3), "r"(b0), "r"(b1));
}

__device__ __forceinline__ void ldsm_x4(unsigned& r0, unsigned& r1, unsigned& r2, unsigned& r3,
                                        unsigned addr) {
    asm volatile("ldmatrix.sync.aligned.m8n8.x4.shared.b16 {%0,%1,%2,%3}, [%4];"
                 : "=r"(r0), "=r"(r1), "=r"(r2), "=r"(r3) : "r"(addr));
}

__device__ __forceinline__ unsigned smem_u32(const void* p) {
    return (unsigned)__cvta_generic_to_shared(p);
}

// load 4 B-fragments (uint2 each) from 2 consecutive uint4
__device__ __forceinline__ void ldw4(uint2* bw, const uint4* p) {
    uint4 a = p[0], b = p[1];
    bw[0] = make_uint2(a.x, a.y); bw[1] = make_uint2(a.z, a.w);
    bw[2] = make_uint2(b.x, b.y); bw[3] = make_uint2(b.z, b.w);
}

__device__ __forceinline__ long long get_count(const void* np, int i, int is64) {
    if (is64) return ((const long long*)np)[i];
    return (long long)((const int*)np)[i];
}

// ---------------- small setup kernels ----------------
__global__ void scan_offsets(const void* __restrict__ np, int Bn) {
    __shared__ long long part[256];
    __shared__ int s_is64;
    if (threadIdx.x == 0) {
        const int* p32 = (const int*)np;
        int is64 = 1;
        for (int i = 1; i < 7 && i < 2 * Bn; i += 2)
            if (p32[i] != 0) is64 = 0;
        s_is64 = is64;
    }
    __syncthreads();
    const int is64 = s_is64;
    const int chunk = (Bn + 255) / 256;
    const int c0 = threadIdx.x * chunk;
    long long s = 0;
    for (int i = 0; i < chunk; i++) {
        int idx = c0 + i;
        if (idx < Bn) s += get_count(np, idx, is64);
    }
    part[threadIdx.x] = s;
    __syncthreads();
    if (threadIdx.x == 0) {
        long long r = 0;
        for (int i = 0; i < 256; i++) { long long t = part[i]; part[i] = r; r += t; }
    }
    __syncthreads();
    long long base = part[threadIdx.x];
    for (int i = 0; i < chunk; i++) {
        int idx = c0 + i;
        if (idx < Bn) {
            d_offs[idx] = base;
            base += get_count(np, idx, is64);
            if (idx == Bn - 1) d_offs[Bn] = base;
        }
    }
}

// fused: blocks [0,Bn) fill seg ids; blocks [Bn, ...) zero d_sums
__global__ void fill_seg_zero(int Bn) {
    int b = blockIdx.x;
    if (b < Bn) {
        long long lo = d_offs[b], hi = d_offs[b + 1];
        for (long long i = lo + threadIdx.x; i < hi; i += blockDim.x)
            d_seg[i] = b;
    } else {
        int i = (b - Bn) * blockDim.x + threadIdx.x;
        if (i < Bn * DOUT) d_sums[i] = 0.f;
    }
}

// pack weights into lane-major uint4 layout
__global__ void cvt_weights(const float* __restrict__ W1,
                            const float* __restrict__ W2,
                            const float* __restrict__ W3) {
    int i = blockIdx.x * 256 + threadIdx.x;   // 32 blocks x 256 = 8192 threads
    // W2r4 [8192]
    if (i < 8192) {
        int pair = i & 1, lane = (i >> 1) & 31, h = (i >> 6) & 1, nq = (i >> 7) & 3, c = i >> 9;
        int g = lane >> 2, tg = lane & 3;
        int k = 16 * c + 2 * tg;
        uint4 out;
        {
            int t = 2 * pair;
            int n = 64 * nq + 32 * h + 8 * t + g;
            out.x = h2u(W2[k * HDIM + n],       W2[(k + 1) * HDIM + n]);
            out.y = h2u(W2[(k + 8) * HDIM + n], W2[(k + 9) * HDIM + n]);
        }
        {
            int t = 2 * pair + 1;
            int n = 64 * nq + 32 * h + 8 * t + g;
            out.z = h2u(W2[k * HDIM + n],       W2[(k + 1) * HDIM + n]);
            out.w = h2u(W2[(k + 8) * HDIM + n], W2[(k + 9) * HDIM + n]);
        }
        d_W2r4[i] = out;
    }
    // W3r4 [4096]
    if (i < 4096) {
        int pair = i & 1, lane = (i >> 1) & 31, nq = (i >> 6) & 3, c = i >> 8;
        int g = lane >> 2, tg = lane & 3;
        int k = 16 * c + 2 * tg;
        uint4 out;
        {
            int t = 2 * pair;
            int n = 32 * nq + 8 * t + g;
            out.x = h2u(W3[k * DOUT + n],       W3[(k + 1) * DOUT + n]);
            out.y = h2u(W3[(k + 8) * DOUT + n], W3[(k + 9) * DOUT + n]);
        }
        {
            int t = 2 * pair + 1;
            int n = 32 * nq + 8 * t + g;
            out.z = h2u(W3[k * DOUT + n],       W3[(k + 1) * DOUT + n]);
            out.w = h2u(W3[(k + 8) * DOUT + n], W3[(k + 9) * DOUT + n]);
        }
        d_W3r4[i] = out;
    }
    // W1r4 [512]
    if (i < 512) {
        int pair = i & 1, lane = (i >> 1) & 31, h = (i >> 6) & 1, nq = (i >> 7) & 3;
        int g = lane >> 2, tg = lane & 3;
        int k = 2 * tg;
        uint4 out;
        {
            int t = 2 * pair;
            int n = 64 * nq + 32 * h + 8 * t + g;
            out.x = h2u(W1[k * HDIM + n],       W1[(k + 1) * HDIM + n]);
            out.y = h2u(W1[(k + 8) * HDIM + n], W1[(k + 9) * HDIM + n]);
        }
        {
            int t = 2 * pair + 1;
            int n = 64 * nq + 32 * h + 8 * t + g;
            out.z = h2u(W1[k * HDIM + n],       W1[(k + 1) * HDIM + n]);
            out.w = h2u(W1[(k + 8) * HDIM + n], W1[(k + 9) * HDIM + n]);
        }
        d_W1r4[i] = out;
    }
}

// ---------------- in-register LN + ReLU -> fp16 smem (R9 3-barrier version) ----------------
__device__ __forceinline__ void ln_relu_reg(
    float4 (&acc)[2][8], __half* __restrict__ sbufh,
    const float* __restrict__ bi, const float* __restrict__ ga, const float* __restrict__ be,
    float* __restrict__ red_s, float* __restrict__ red_q,
    float* __restrict__ s_m, float* __restrict__ s_r,
    int g, int tg, int n0, int rb, int nq, int tid)
{
    #pragma unroll
    for (int t = 0; t < 8; t++) {
        const float2 bb = *(const float2*)(bi + n0 + 8 * t + 2 * tg);
        #pragma unroll
        for (int m = 0; m < 2; m++) {
            acc[m][t].x += bb.x; acc[m][t].y += bb.y;
            acc[m][t].z += bb.x; acc[m][t].w += bb.y;
        }
    }
    float s[2][2], q[2][2];
    #pragma unroll
    for (int m = 0; m < 2; m++) {
        float sl = 0.f, ql = 0.f, sh = 0.f, qh = 0.f;
        #pragma unroll
        for (int t = 0; t < 8; t++) {
            float4 v = acc[m][t];
            sl += v.x + v.y;  ql += v.x * v.x + v.y * v.y;
            sh += v.z + v.w;  qh += v.z * v.z + v.w * v.w;
        }
        s[m][0] = sl; q[m][0] = ql; s[m][1] = sh; q[m][1] = qh;
    }
    #pragma unroll
    for (int o = 1; o <= 2; o <<= 1) {
        #pragma unroll
        for (int m = 0; m < 2; m++) {
            #pragma unroll
            for (int h = 0; h < 2; h++) {
                s[m][h] += __shfl_xor_sync(0xffffffffu, s[m][h], o);
                q[m][h] += __shfl_xor_sync(0xffffffffu, q[m][h], o);
            }
        }
    }
    if (tg == 0) {
        #pragma unroll
        for (int m = 0; m < 2; m++) {
            red_s[(rb + 16 * m + g) * 4 + nq]     = s[m][0];
            red_q[(rb + 16 * m + g) * 4 + nq]     = q[m][0];
            red_s[(rb + 16 * m + g + 8) * 4 + nq] = s[m][1];
            red_q[(rb + 16 * m + g + 8) * 4 + nq] = q[m][1];
        }
    }
    __syncthreads();
    if (tid < MT) {
        float ss = 0.f, qq = 0.f;
        #pragma unroll
        for (int w = 0; w < 4; w++) { ss += red_s[tid * 4 + w]; qq += red_q[tid * 4 + w]; }
        float mm = ss * (1.f / 256.f);
        s_m[tid] = mm;
        s_r[tid] = rsqrtf(qq * (1.f / 256.f) - mm * mm + 1e-5f);
    }
    __syncthreads();
    #pragma unroll
    for (int m = 0; m < 2; m++) {
        const int rl_ = rb + 16 * m + g;
        const float ml = s_m[rl_],     rl = s_r[rl_];
        const float mh = s_m[rl_ + 8], rh = s_r[rl_ + 8];
        #pragma unroll
        for (int t = 0; t < 8; t++) {
            const int col = n0 + 8 * t + 2 * tg;
            const float2 gg = *(const float2*)(ga + col);
            const float2 ee = *(const float2*)(be + col);
            unsigned lo = h2u(fmaxf((acc[m][t].x - ml) * rl * gg.x + ee.x, 0.f),
                              fmaxf((acc[m][t].y - ml) * rl * gg.y + ee.y, 0.f));
            unsigned hi = h2u(fmaxf((acc[m][t].z - mh) * rh * gg.x + ee.x, 0.f),
                              fmaxf((acc[m][t].w - mh) * rh * gg.y + ee.y, 0.f));
            *(unsigned*)(sbufh + rl_ * PITCHH + col)       = lo;
            *(unsigned*)(sbufh + (rl_ + 8) * PITCHH + col) = hi;
        }
    }
    __syncthreads();
}

// ---------------- main fused persistent kernel (2 CTAs/SM, 64-pt tiles) ----------------
__global__ __launch_bounds__(TPB, 2)
void mlp_mma(const float* __restrict__ z,
             const float* __restrict__ b1, const float* __restrict__ g1, const float* __restrict__ be1,
             const float* __restrict__ b2, const float* __restrict__ g2, const float* __restrict__ be2,
             const float* __restrict__ b3,
             int Npts, int ntiles)
{
    extern __shared__ char smem_raw[];
    __half* sbufh = (__half*)smem_raw;              // 64*PITCHH halves
    __half* zsh   = sbufh + MT * PITCHH;            // 64*ZPH halves
    float* sb1   = (float*)(zsh + MT * ZPH);
    float* sg1   = sb1 + HDIM;
    float* sbe1  = sg1 + HDIM;
    float* sb2   = sbe1 + HDIM;
    float* sg2   = sb2 + HDIM;
    float* sbe2  = sg2 + HDIM;
    float* sb3   = sbe2 + HDIM;                     // 128
    float* red_s = sb3 + DOUT;                      // 256
    float* red_q = red_s + 256;                     // 256
    float* s_m   = red_q + 256;                     // 64
    float* s_r   = s_m + MT;                        // 64
    int*   ssg   = (int*)(s_r + MT);                // 64
    float* fbuf  = (float*)smem_raw;                // layer-3 C view, pitch FPITCH

    const int tid = threadIdx.x;
    const int warp = tid >> 5, lane = tid & 31;
    const int g = lane >> 2, tg = lane & 3;
    const int nq = warp & 3, mh = warp >> 2;
    const int rb = 32 * mh;                         // row base (32-row half)
    const int n0 = 64 * nq;                         // 64-col slice for H=256 layers
    const int n3 = 32 * nq;                         // 32-col slice for DOUT=128

    // lane-major weight base pointers
    const uint4* wbase1 = d_W1r4 + (nq * 128 + lane * 2);
    const uint4* wbase2 = d_W2r4 + (nq * 128 + lane * 2);
    const uint4* wbase3 = d_W3r4 + (nq * 64 + lane * 2);

    // LDSM lane addressing (rows 0..31 within half, 2 m-tiles)
    const int lrow = (lane & 7) + ((lane >> 3) & 1) * 8;
    const int lcol = (lane >> 4) * 8;
    const unsigned zbase = smem_u32(zsh);
    const unsigned lds_z0 = zbase + (unsigned)(((rb + lrow) * ZPH + lcol) * 2);
    const unsigned lds_z1 = zbase + (unsigned)(((rb + 16 + lrow) * ZPH + lcol) * 2);
    const unsigned hbase = smem_u32(sbufh);
    const unsigned lds_a0 = hbase + (unsigned)(((rb + lrow) * PITCHH + lcol) * 2);
    const unsigned lds_a1 = hbase + (unsigned)(((rb + 16 + lrow) * PITCHH + lcol) * 2);

    // ---- one-time param load ----
    sb1[tid] = b1[tid]; sg1[tid] = g1[tid]; sbe1[tid] = be1[tid];
    sb2[tid] = b2[tid]; sg2[tid] = g2[tid]; sbe2[tid] = be2[tid];
    if (tid < DOUT) sb3[tid] = b3[tid];
    __syncthreads();

    uint2 bw0[4], bw1[4];   // B-fragment pipeline registers
    float4 acc[2][8];

    for (int tile = blockIdx.x; tile < ntiles; tile += gridDim.x) {
        const int p0 = tile * MT;
        const int npts = min(MT, Npts - p0);

        // layer-1 weights (L1-resident): both halves
        uint2 w1l[4], w1h[4];
        ldw4(w1l, wbase1);
        ldw4(w1h, wbase1 + 64);

        // ---- z tile + seg ids ----
        {
            const float4* z4 = (const float4*)(z + (long long)p0 * DIN);
            int pi = tid >> 2, ci = tid & 3;
            float4 v = make_float4(0.f, 0.f, 0.f, 0.f);
            if (pi < npts) v = z4[pi * 4 + ci];
            *(uint2*)(zsh + pi * ZPH + 4 * ci) = make_uint2(h2u(v.x, v.y), h2u(v.z, v.w));
            if (tid < MT) ssg[tid] = (tid < npts) ? d_seg[p0 + tid] : 0;
        }
        __syncthreads();

        // ================= Layer 1: [64x16] @ [16x256], single k16 chunk =================
        #pragma unroll
        for (int m = 0; m < 2; m++)
            #pragma unroll
            for (int t = 0; t < 8; t++) acc[m][t] = make_float4(0.f, 0.f, 0.f, 0.f);
        {
            unsigned a[2][4];
            ldsm_x4(a[0][0], a[0][1], a[0][2], a[0][3], lds_z0);
            ldsm_x4(a[1][0], a[1][1], a[1][2], a[1][3], lds_z1);
            #pragma unroll
            for (int t = 0; t < 4; t++)
                #pragma unroll
                for (int m = 0; m < 2; m++)
                    mma_f16(acc[m][t], a[m][0], a[m][1], a[m][2], a[m][3],
                            w1l[t].x, w1l[t].y);
            #pragma unroll
            for (int t = 0; t < 4; t++)
                #pragma unroll
                for (int m = 0; m < 2; m++)
                    mma_f16(acc[m][4 + t], a[m][0], a[m][1], a[m][2], a[m][3],
                            w1h[t].x, w1h[t].y);
        }
        // preload layer-2 chunk0 low half (latency hidden under LN1)
        ldw4(bw0, wbase2);

        ln_relu_reg(acc, sbufh, sb1, sg1, sbe1, red_s, red_q, s_m, s_r, g, tg, n0, rb, nq, tid);

        // ================= Layer 2: [64x256] @ [256x256], 16 k16 chunks =================
        #pragma unroll
        for (int m = 0; m < 2; m++)
            #pragma unroll
            for (int t = 0; t < 8; t++) acc[m][t] = make_float4(0.f, 0.f, 0.f, 0.f);

        #pragma unroll 1
        for (int c = 0; c < 16; c++) {
            // prefetch high half of chunk c
            ldw4(bw1, wbase2 + c * 512 + 64);
            unsigned a[2][4];
            ldsm_x4(a[0][0], a[0][1], a[0][2], a[0][3], lds_a0 + (unsigned)(32 * c));
            ldsm_x4(a[1][0], a[1][1], a[1][2], a[1][3], lds_a1 + (unsigned)(32 * c));
            // compute low half (t=0..3) with bw0
            #pragma unroll
            for (int t = 0; t < 4; t++)
                #pragma unroll
                for (int m = 0; m < 2; m++)
                    mma_f16(acc[m][t], a[m][0], a[m][1], a[m][2], a[m][3],
                            bw0[t].x, bw0[t].y);
            // prefetch low half of chunk c+1
            if (c + 1 < 16) ldw4(bw0, wbase2 + (c + 1) * 512);
            // compute high half (t=4..7) with bw1
            #pragma unroll
            for (int t = 0; t < 4; t++)
                #pragma unroll
                for (int m = 0; m < 2; m++)
                    mma_f16(acc[m][4 + t], a[m][0], a[m][1], a[m][2], a[m][3],
                            bw1[t].x, bw1[t].y);
        }
        // preload layer-3 chunk0 (hidden under LN2)
        ldw4(bw0, wbase3);

        ln_relu_reg(acc, sbufh, sb2, sg2, sbe2, red_s, red_q, s_m, s_r, g, tg, n0, rb, nq, tid);

        // ================= Layer 3: [64x256] @ [256x128] =================
        {
            float4 acc3[2][4];
            #pragma unroll
            for (int m = 0; m < 2; m++)
                #pragma unroll
                for (int t = 0; t < 4; t++) acc3[m][t] = make_float4(0.f, 0.f, 0.f, 0.f);

            #pragma unroll 1
            for (int c = 0; c < 16; c += 2) {
                ldw4(bw1, wbase3 + (c + 1) * 256);
                {
                    unsigned a[2][4];
                    ldsm_x4(a[0][0], a[0][1], a[0][2], a[0][3], lds_a0 + (unsigned)(32 * c));
                    ldsm_x4(a[1][0], a[1][1], a[1][2], a[1][3], lds_a1 + (unsigned)(32 * c));
                    #pragma unroll
                    for (int t = 0; t < 4; t++)
                        #pragma unroll
                        for (int m = 0; m < 2; m++)
                            mma_f16(acc3[m][t], a[m][0], a[m][1], a[m][2], a[m][3],
                                    bw0[t].x, bw0[t].y);
                }
                if (c + 2 < 16) ldw4(bw0, wbase3 + (c + 2) * 256);
                {
                    unsigned a[2][4];
                    ldsm_x4(a[0][0], a[0][1], a[0][2], a[0][3], lds_a0 + (unsigned)(32 * (c + 1)));
                    ldsm_x4(a[1][0], a[1][1], a[1][2], a[1][3], lds_a1 + (unsigned)(32 * (c + 1)));
                    #pragma unroll
                    for (int t = 0; t < 4; t++)
                        #pragma unroll
                        for (int m = 0; m < 2; m++)
                            mma_f16(acc3[m][t], a[m][0], a[m][1], a[m][2], a[m][3],
                                    bw1[t].x, bw1[t].y);
                }
            }
            __syncthreads();   // all sbuf A reads done before overwriting with C3 (float view)
            #pragma unroll
            for (int m = 0; m < 2; m++)
                #pragma unroll
                for (int t = 0; t < 4; t++) {
                    float* cr = fbuf + (rb + 16 * m + g) * FPITCH + n3 + 8 * t + 2 * tg;
                    cr[0] = acc3[m][t].x; cr[1] = acc3[m][t].y;
                    cr[8 * FPITCH] = acc3[m][t].z; cr[8 * FPITCH + 1] = acc3[m][t].w;
                }
        }
        __syncthreads();

        // ================= epilogue: bias + run-length segment accumulate =================
        {
            const int f = tid & (DOUT - 1);
            const int half = tid >> 7;
            const int ps = half * 32;
            const int pe = min(ps + 32, npts);
            if (ps < pe) {
                const float bf = sb3[f];
                int cur = ssg[ps];
                float run = 0.f;
                for (int p = ps; p < pe; p++) {
                    float phi = fbuf[p * FPITCH + f] + bf;
                    int sp = ssg[p];
                    if (sp != cur) {
                        atomicAdd(&d_sums[cur * DOUT + f], run);
                        run = 0.f;
                        cur = sp;
                    }
                    run += phi;
                }
                atomicAdd(&d_sums[cur * DOUT + f], run);
            }
        }
        __syncthreads();   // fbuf/ssg reads done before next iteration overwrites
    }
}

__global__ void finalize_means(int Bn) {
    int i = blockIdx.x * blockDim.x + threadIdx.x;
    if (i < Bn * DOUT) {
        int b = i >> 7;
        float cnt = (float)(d_offs[b + 1] - d_offs[b]);
        d_emb[i] = d_sums[i] / cnt;
    }
}

__global__ void broadcast_out(float4* __restrict__ out, long long total4) {
    long long i = (long long)blockIdx.x * blockDim.x + threadIdx.x;
    if (i < total4) {
        long long p = i >> 5;
        int c = (int)(i & 31);
        const float4* emb4 = reinterpret_cast<const float4*>(d_emb);
        out[i] = emb4[(long long)d_seg[p] * 32 + c];
    }
}

extern "C" void kernel_launch(void* const* d_in, const int* in_sizes, int n_in,
                              void* d_out, int out_size) {
    const float* z   = (const float*)d_in[0];
    const float* W1  = (const float*)d_in[1];
    const float* b1  = (const float*)d_in[2];
    const float* g1  = (const float*)d_in[3];
    const float* be1 = (const float*)d_in[4];
    const float* W2  = (const float*)d_in[5];
    const float* b2  = (const float*)d_in[6];
    const float* g2  = (const float*)d_in[7];
    const float* be2 = (const float*)d_in[8];
    const float* W3  = (const float*)d_in[9];
    const float* b3  = (const float*)d_in[10];
    const void*  np  = d_in[11];

    const int Bn = in_sizes[11];
    const int N  = in_sizes[0] / DIN;

    static const size_t SMEM_BYTES =
        (MT * PITCHH + MT * ZPH) * sizeof(__half)
        + (6 * HDIM + DOUT + 256 + 256 + 2 * MT) * sizeof(float)
        + MT * sizeof(int);
    cudaFuncSetAttribute(mlp_mma, cudaFuncAttributeMaxDynamicSharedMemorySize,
                         (int)SMEM_BYTES);

    int dev = 0, nsm = 148;
    cudaGetDevice(&dev);
    cudaDeviceGetAttribute(&nsm, cudaDevAttrMultiProcessorCount, dev);

    // mlp_mma kept as the 4th launch (ncu capture slot)
    scan_offsets<<<1, 256>>>(np, Bn);
    cvt_weights<<<32, 256>>>(W1, W2, W3);
    fill_seg_zero<<<Bn + (Bn * DOUT + 127) / 128, 128>>>(Bn);

    const int ntiles = (N + MT - 1) / MT;
    int grid = 2 * nsm;
    if (grid > ntiles) grid = ntiles;
    mlp_mma<<<grid, TPB, SMEM_BYTES>>>(z, b1, g1, be1, b2, g2, be2, b3, N, ntiles);

    finalize_means<<<(Bn * DOUT + 255) / 256, 256>>>(Bn);

    const long long total4 = (long long)N * (DOUT / 4);
    broadcast_out<<<(int)((total4 + 255) / 256), 256>>>((float4*)d_out, total4);
}

// round 16
// speedup vs baseline: 1.0809x; 1.0546x over previous
#include <cuda_runtime.h>
#include <cuda_fp16.h>
#include <cstdint>

#define TPB    256
#define MT     64          // points per tile
#define HDIM   256
#define DIN    16
#define DOUT   128
#define PITCHH 264         // sbuf pitch in halves; row stride 528B -> LDSM conflict-free
#define FPITCH 132         // float view pitch for layer-3 C / epilogue
#define ZPH    24          // z tile pitch in halves
#define BMAX   4096
#define NMAX   1100000

// ---------------- device scratch (no allocations allowed) ----------------
__device__ long long d_offs[BMAX + 1];
__device__ int       d_seg[NMAX];
__device__ float     d_sums[BMAX * DOUT];
__device__ float     d_inv[BMAX];
// fp16 k16-chunk packed weights: index (kc*N + n)*4 + tg -> uint2
__device__ uint2     d_W1h[1  * HDIM * 4];
__device__ uint2     d_W2h[16 * HDIM * 4];
__device__ uint2     d_W3h[16 * DOUT * 4];

// ---------------- helpers ----------------
__device__ __forceinline__ unsigned h2u(float a, float b) {
    __half2 h = __floats2half2_rn(a, b);
    return *reinterpret_cast<unsigned*>(&h);
}

__device__ __forceinline__ void mma_f16(float4& d,
                                        unsigned a0, unsigned a1, unsigned a2, unsigned a3,
                                        unsigned b0, unsigned b1) {
    asm volatile(
        "mma.sync.aligned.m16n8k16.row.col.f32.f16.f16.f32 "
        "{%0,%1,%2,%3}, {%4,%5,%6,%7}, {%8,%9}, {%0,%1,%2,%3};"
        : "+f"(d.x), "+f"(d.y), "+f"(d.z), "+f"(d.w)
        : "r"(a0), "r"(a1), "r"(a2), "r"(a3), "r"(b0), "r"(b1));
}

__device__ __forceinline__ void ldsm_x4(unsigned& r0, unsigned& r1, unsigned& r2, unsigned& r3,
                                        unsigned addr) {
    asm volatile("ldmatrix.sync.aligned.m8n8.x4.shared.b16 {%0,%1,%2,%3}, [%4];"
                 : "=r"(r0), "=r"(r1), "=r"(r2), "=r"(r3) : "r"(addr));
}

__device__ __forceinline__ unsigned smem_u32(const void* p) {
    return (unsigned)__cvta_generic_to_shared(p);
}

__device__ __forceinline__ long long get_count(const void* np, int i, int is64) {
    if (is64) return ((const long long*)np)[i];
    return (long long)((const int*)np)[i];
}

// ---------------- small setup kernels ----------------
__global__ void scan_offsets(const void* __restrict__ np, int Bn) {
    __shared__ long long part[256];
    __shared__ int s_is64;
    if (threadIdx.x == 0) {
        const int* p32 = (const int*)np;
        int is64 = 1;
        for (int i = 1; i < 7 && i < 2 * Bn; i += 2)
            if (p32[i] != 0) is64 = 0;
        s_is64 = is64;
    }
    __syncthreads();
    const int is64 = s_is64;
    const int chunk = (Bn + 255) / 256;
    const int c0 = threadIdx.x * chunk;
    long long s = 0;
    for (int i = 0; i < chunk; i++) {
        int idx = c0 + i;
        if (idx < Bn) s += get_count(np, idx, is64);
    }
    part[threadIdx.x] = s;
    __syncthreads();
    if (threadIdx.x == 0) {
        long long r = 0;
        for (int i = 0; i < 256; i++) { long long t = part[i]; part[i] = r; r += t; }
    }
    __syncthreads();
    long long base = part[threadIdx.x];
    for (int i = 0; i < chunk; i++) {
        int idx = c0 + i;
        if (idx < Bn) {
            d_offs[idx] = base;
            long long cnt = get_count(np, idx, is64);
            d_inv[idx] = 1.f / (float)cnt;
            base += cnt;
            if (idx == Bn - 1) d_offs[Bn] = base;
        }
    }
}

// fused: blocks [0,Bn) fill seg ids; blocks [Bn, ...) zero d_sums
__global__ void fill_seg_zero(int Bn) {
    int b = blockIdx.x;
    if (b < Bn) {
        long long lo = d_offs[b], hi = d_offs[b + 1];
        for (long long i = lo + threadIdx.x; i < hi; i += blockDim.x)
            d_seg[i] = b;
    } else {
        int i = (b - Bn) * blockDim.x + threadIdx.x;
        if (i < Bn * DOUT) d_sums[i] = 0.f;
    }
}

// pack weights into fp16 k16-chunk layout
__global__ void cvt_weights(const float* __restrict__ W1,
                            const float* __restrict__ W2,
                            const float* __restrict__ W3) {
    int i = blockIdx.x * 256 + threadIdx.x;   // launch >= 16384 threads
    if (i < 16 * HDIM * 4) {
        int tg = i & 3, n = (i >> 2) & (HDIM - 1), kc = i >> 10;
        int k = 16 * kc + 2 * tg;
        d_W2h[i] = make_uint2(h2u(W2[k * HDIM + n],       W2[(k + 1) * HDIM + n]),
                              h2u(W2[(k + 8) * HDIM + n], W2[(k + 9) * HDIM + n]));
    }
    if (i < 16 * DOUT * 4) {
        int tg = i & 3, n = (i >> 2) & (DOUT - 1), kc = i >> 9;
        int k = 16 * kc + 2 * tg;
        d_W3h[i] = make_uint2(h2u(W3[k * DOUT + n],       W3[(k + 1) * DOUT + n]),
                              h2u(W3[(k + 8) * DOUT + n], W3[(k + 9) * DOUT + n]));
    }
    if (i < 1 * HDIM * 4) {
        int tg = i & 3, n = i >> 2;
        int k = 2 * tg;
        d_W1h[i] = make_uint2(h2u(W1[k * HDIM + n],       W1[(k + 1) * HDIM + n]),
                              h2u(W1[(k + 8) * HDIM + n], W1[(k + 9) * HDIM + n]));
    }
}

// ---------------- in-register LN + ReLU -> fp16 smem (2m x 8n warp layout) ----------------
__device__ __forceinline__ void ln_relu_reg(
    float4 (&acc)[2][8], __half* __restrict__ sbufh,
    const float* __restrict__ bi, const float* __restrict__ ga, const float* __restrict__ be,
    float* __restrict__ red_s, float* __restrict__ red_q,
    float* __restrict__ s_m, float* __restrict__ s_r,
    int g, int tg, int n0, int rb, int nq, int tid)
{
    #pragma unroll
    for (int t = 0; t < 8; t++) {
        const float2 bb = *(const float2*)(bi + n0 + 8 * t + 2 * tg);
        #pragma unroll
        for (int m = 0; m < 2; m++) {
            acc[m][t].x += bb.x; acc[m][t].y += bb.y;
            acc[m][t].z += bb.x; acc[m][t].w += bb.y;
        }
    }
    float s[2][2], q[2][2];
    #pragma unroll
    for (int m = 0; m < 2; m++) {
        float sl = 0.f, ql = 0.f, sh = 0.f, qh = 0.f;
        #pragma unroll
        for (int t = 0; t < 8; t++) {
            float4 v = acc[m][t];
            sl += v.x + v.y;  ql += v.x * v.x + v.y * v.y;
            sh += v.z + v.w;  qh += v.z * v.z + v.w * v.w;
        }
        s[m][0] = sl; q[m][0] = ql; s[m][1] = sh; q[m][1] = qh;
    }
    #pragma unroll
    for (int o = 1; o <= 2; o <<= 1) {
        #pragma unroll
        for (int m = 0; m < 2; m++) {
            #pragma unroll
            for (int h = 0; h < 2; h++) {
                s[m][h] += __shfl_xor_sync(0xffffffffu, s[m][h], o);
                q[m][h] += __shfl_xor_sync(0xffffffffu, q[m][h], o);
            }
        }
    }
    if (tg == 0) {
        #pragma unroll
        for (int m = 0; m < 2; m++) {
            red_s[(rb + 16 * m + g) * 4 + nq]     = s[m][0];
            red_q[(rb + 16 * m + g) * 4 + nq]     = q[m][0];
            red_s[(rb + 16 * m + g + 8) * 4 + nq] = s[m][1];
            red_q[(rb + 16 * m + g + 8) * 4 + nq] = q[m][1];
        }
    }
    __syncthreads();
    if (tid < MT) {
        float ss = 0.f, qq = 0.f;
        #pragma unroll
        for (int w = 0; w < 4; w++) { ss += red_s[tid * 4 + w]; qq += red_q[tid * 4 + w]; }
        float mm = ss * (1.f / 256.f);
        s_m[tid] = mm;
        s_r[tid] = rsqrtf(qq * (1.f / 256.f) - mm * mm + 1e-5f);
    }
    __syncthreads();
    #pragma unroll
    for (int m = 0; m < 2; m++) {
        const int rl_ = rb + 16 * m + g;
        const float ml = s_m[rl_],     rl = s_r[rl_];
        const float mh = s_m[rl_ + 8], rh = s_r[rl_ + 8];
        #pragma unroll
        for (int t = 0; t < 8; t++) {
            const int col = n0 + 8 * t + 2 * tg;
            const float2 gg = *(const float2*)(ga + col);
            const float2 ee = *(const float2*)(be + col);
            unsigned lo = h2u(fmaxf((acc[m][t].x - ml) * rl * gg.x + ee.x, 0.f),
                              fmaxf((acc[m][t].y - ml) * rl * gg.y + ee.y, 0.f));
            unsigned hi = h2u(fmaxf((acc[m][t].z - mh) * rh * gg.x + ee.x, 0.f),
                              fmaxf((acc[m][t].w - mh) * rh * gg.y + ee.y, 0.f));
            *(unsigned*)(sbufh + rl_ * PITCHH + col)       = lo;
            *(unsigned*)(sbufh + (rl_ + 8) * PITCHH + col) = hi;
        }
    }
    __syncthreads();
}

// ---------------- main fused persistent kernel (R9 structure) ----------------
__global__ __launch_bounds__(TPB, 2)
void mlp_mma(const float* __restrict__ z,
             const float* __restrict__ b1, const float* __restrict__ g1, const float* __restrict__ be1,
             const float* __restrict__ b2, const float* __restrict__ g2, const float* __restrict__ be2,
             const float* __restrict__ b3,
             int Npts, int ntiles)
{
    extern __shared__ char smem_raw[];
    __half* sbufh = (__half*)smem_raw;              // 64*PITCHH halves
    __half* zsh   = sbufh + MT * PITCHH;            // 64*ZPH halves
    float* sb1   = (float*)(zsh + MT * ZPH);
    float* sg1   = sb1 + HDIM;
    float* sbe1  = sg1 + HDIM;
    float* sb2   = sbe1 + HDIM;
    float* sg2   = sb2 + HDIM;
    float* sbe2  = sg2 + HDIM;
    float* sb3   = sbe2 + HDIM;                     // 128
    float* red_s = sb3 + DOUT;                      // 256
    float* red_q = red_s + 256;                     // 256
    float* s_m   = red_q + 256;                     // 64
    float* s_r   = s_m + MT;                        // 64
    int*   ssg   = (int*)(s_r + MT);                // 64
    float* fbuf  = (float*)smem_raw;                // layer-3 C view, pitch FPITCH

    const int tid = threadIdx.x;
    const int warp = tid >> 5, lane = tid & 31;
    const int g = lane >> 2, tg = lane & 3;
    const int nq = warp & 3, mh = warp >> 2;
    const int rb = 32 * mh;                         // row base (32-row half)
    const int n0 = 64 * nq;                         // 64-col slice for H=256 layers
    const int n3 = 32 * nq;                         // 32-col slice for DOUT=128

    // LDSM lane addressing (rows 0..31, 2 m-tiles)
    const int lrow = (lane & 7) + ((lane >> 3) & 1) * 8;
    const int lcol = (lane >> 4) * 8;
    const unsigned zbase = smem_u32(zsh);
    const unsigned lds_z0 = zbase + (unsigned)(((rb + lrow) * ZPH + lcol) * 2);
    const unsigned lds_z1 = zbase + (unsigned)(((rb + 16 + lrow) * ZPH + lcol) * 2);
    const unsigned hbase = smem_u32(sbufh);
    const unsigned lds_a0 = hbase + (unsigned)(((rb + lrow) * PITCHH + lcol) * 2);
    const unsigned lds_a1 = hbase + (unsigned)(((rb + 16 + lrow) * PITCHH + lcol) * 2);

    // ---- one-time param load ----
    sb1[tid] = b1[tid]; sg1[tid] = g1[tid]; sbe1[tid] = be1[tid];
    sb2[tid] = b2[tid]; sg2[tid] = g2[tid]; sbe2[tid] = be2[tid];
    if (tid < DOUT) sb3[tid] = b3[tid];
    __syncthreads();

    uint2 bw0[4], bw1[4];   // B-fragment pipeline registers
    float4 acc[2][8];

    for (int tile = blockIdx.x; tile < ntiles; tile += gridDim.x) {
        const int p0 = tile * MT;
        const int npts = min(MT, Npts - p0);

        uint2 w1h[8];
        #pragma unroll
        for (int t = 0; t < 8; t++)
            w1h[t] = d_W1h[(n0 + 8 * t + g) * 4 + tg];

        // ---- z tile + seg ids ----
        {
            const float4* z4 = (const float4*)(z + (long long)p0 * DIN);
            int pi = tid >> 2, ci = tid & 3;
            float4 v = make_float4(0.f, 0.f, 0.f, 0.f);
            if (pi < npts) v = z4[pi * 4 + ci];
            *(uint2*)(zsh + pi * ZPH + 4 * ci) = make_uint2(h2u(v.x, v.y), h2u(v.z, v.w));
            if (tid < MT) ssg[tid] = (tid < npts) ? d_seg[p0 + tid] : 0;
        }
        __syncthreads();

        // ================= Layer 1: [64x16] @ [16x256], single k16 chunk =================
        #pragma unroll
        for (int m = 0; m < 2; m++)
            #pragma unroll
            for (int t = 0; t < 8; t++) acc[m][t] = make_float4(0.f, 0.f, 0.f, 0.f);
        {
            unsigned a[2][4];
            ldsm_x4(a[0][0], a[0][1], a[0][2], a[0][3], lds_z0);
            ldsm_x4(a[1][0], a[1][1], a[1][2], a[1][3], lds_z1);
            #pragma unroll
            for (int t = 0; t < 8; t++)
                #pragma unroll
                for (int m = 0; m < 2; m++)
                    mma_f16(acc[m][t], a[m][0], a[m][1], a[m][2], a[m][3],
                            w1h[t].x, w1h[t].y);
        }
        // preload layer-2 chunk0 low half (latency hidden under LN1)
        #pragma unroll
        for (int t = 0; t < 4; t++)
            bw0[t] = d_W2h[(n0 + 8 * t + g) * 4 + tg];

        ln_relu_reg(acc, sbufh, sb1, sg1, sbe1, red_s, red_q, s_m, s_r, g, tg, n0, rb, nq, tid);

        // ================= Layer 2: [64x256] @ [256x256], 16 k16 chunks =================
        #pragma unroll
        for (int m = 0; m < 2; m++)
            #pragma unroll
            for (int t = 0; t < 8; t++) acc[m][t] = make_float4(0.f, 0.f, 0.f, 0.f);

        #pragma unroll 1
        for (int c = 0; c < 16; c++) {
            // prefetch high half of chunk c
            #pragma unroll
            for (int t = 0; t < 4; t++)
                bw1[t] = d_W2h[(c * HDIM + n0 + 32 + 8 * t + g) * 4 + tg];
            const unsigned koff = (unsigned)(32 * c);
            unsigned a[2][4];
            ldsm_x4(a[0][0], a[0][1], a[0][2], a[0][3], lds_a0 + koff);
            ldsm_x4(a[1][0], a[1][1], a[1][2], a[1][3], lds_a1 + koff);
            // compute low half (t=0..3) with bw0
            #pragma unroll
            for (int t = 0; t < 4; t++)
                #pragma unroll
                for (int m = 0; m < 2; m++)
                    mma_f16(acc[m][t], a[m][0], a[m][1], a[m][2], a[m][3],
                            bw0[t].x, bw0[t].y);
            // prefetch low half of chunk c+1
            if (c + 1 < 16) {
                #pragma unroll
                for (int t = 0; t < 4; t++)
                    bw0[t] = d_W2h[((c + 1) * HDIM + n0 + 8 * t + g) * 4 + tg];
            }
            // compute high half (t=4..7) with bw1
            #pragma unroll
            for (int t = 0; t < 4; t++)
                #pragma unroll
                for (int m = 0; m < 2; m++)
                    mma_f16(acc[m][4 + t], a[m][0], a[m][1], a[m][2], a[m][3],
                            bw1[t].x, bw1[t].y);
        }
        // preload layer-3 chunk0 (hidden under LN2)
        #pragma unroll
        for (int t = 0; t < 4; t++)
            bw0[t] = d_W3h[(n3 + 8 * t + g) * 4 + tg];

        ln_relu_reg(acc, sbufh, sb2, sg2, sbe2, red_s, red_q, s_m, s_r, g, tg, n0, rb, nq, tid);

        // ================= Layer 3: [64x256] @ [256x128] =================
        {
            float4 acc3[2][4];
            #pragma unroll
            for (int m = 0; m < 2; m++)
                #pragma unroll
                for (int t = 0; t < 4; t++) acc3[m][t] = make_float4(0.f, 0.f, 0.f, 0.f);

            #pragma unroll 1
            for (int c = 0; c < 16; c += 2) {
                #pragma unroll
                for (int t = 0; t < 4; t++)
                    bw1[t] = d_W3h[((c + 1) * DOUT + n3 + 8 * t + g) * 4 + tg];
                {
                    const unsigned koff = (unsigned)(32 * c);
                    unsigned a[2][4];
                    ldsm_x4(a[0][0], a[0][1], a[0][2], a[0][3], lds_a0 + koff);
                    ldsm_x4(a[1][0], a[1][1], a[1][2], a[1][3], lds_a1 + koff);
                    #pragma unroll
                    for (int t = 0; t < 4; t++)
                        #pragma unroll
                        for (int m = 0; m < 2; m++)
                            mma_f16(acc3[m][t], a[m][0], a[m][1], a[m][2], a[m][3],
                                    bw0[t].x, bw0[t].y);
                }
                if (c + 2 < 16) {
                    #pragma unroll
                    for (int t = 0; t < 4; t++)
                        bw0[t] = d_W3h[((c + 2) * DOUT + n3 + 8 * t + g) * 4 + tg];
                }
                {
                    const unsigned koff = (unsigned)(32 * (c + 1));
                    unsigned a[2][4];
                    ldsm_x4(a[0][0], a[0][1], a[0][2], a[0][3], lds_a0 + koff);
                    ldsm_x4(a[1][0], a[1][1], a[1][2], a[1][3], lds_a1 + koff);
                    #pragma unroll
                    for (int t = 0; t < 4; t++)
                        #pragma unroll
                        for (int m = 0; m < 2; m++)
                            mma_f16(acc3[m][t], a[m][0], a[m][1], a[m][2], a[m][3],
                                    bw1[t].x, bw1[t].y);
                }
            }
            __syncthreads();   // all sbuf A reads done before overwriting with C3 (float view)
            #pragma unroll
            for (int m = 0; m < 2; m++)
                #pragma unroll
                for (int t = 0; t < 4; t++) {
                    float* cr = fbuf + (rb + 16 * m + g) * FPITCH + n3 + 8 * t + 2 * tg;
                    cr[0] = acc3[m][t].x; cr[1] = acc3[m][t].y;
                    cr[8 * FPITCH] = acc3[m][t].z; cr[8 * FPITCH + 1] = acc3[m][t].w;
                }
        }
        __syncthreads();

        // ================= epilogue: bias + run-length segment accumulate =================
        {
            const int f = tid & (DOUT - 1);
            const int half = tid >> 7;
            const int ps = half * 32;
            const int pe = min(ps + 32, npts);
            if (ps < pe) {
                const float bf = sb3[f];
                int cur = ssg[ps];
                float run = 0.f;
                for (int p = ps; p < pe; p++) {
                    float phi = fbuf[p * FPITCH + f] + bf;
                    int sp = ssg[p];
                    if (sp != cur) {
                        atomicAdd(&d_sums[cur * DOUT + f], run);
                        run = 0.f;
                        cur = sp;
                    }
                    run += phi;
                }
                atomicAdd(&d_sums[cur * DOUT + f], run);
            }
        }
        __syncthreads();   // fbuf/ssg reads done before next iteration overwrites
    }
}

// fused mean + broadcast: out[p, :] = d_sums[seg[p], :] * d_inv[seg[p]]
__global__ void broadcast_out(float4* __restrict__ out, long long total4) {
    long long i = (long long)blockIdx.x * blockDim.x + threadIdx.x;
    if (i < total4) {
        long long p = i >> 5;
        int c = (int)(i & 31);
        int b = d_seg[p];
        const float4* sums4 = reinterpret_cast<const float4*>(d_sums);
        float4 v = sums4[(long long)b * 32 + c];
        float inv = d_inv[b];
        v.x *= inv; v.y *= inv; v.z *= inv; v.w *= inv;
        out[i] = v;
    }
}

extern "C" void kernel_launch(void* const* d_in, const int* in_sizes, int n_in,
                              void* d_out, int out_size) {
    const float* z   = (const float*)d_in[0];
    const float* W1  = (const float*)d_in[1];
    const float* b1  = (const float*)d_in[2];
    const float* g1  = (const float*)d_in[3];
    const float* be1 = (const float*)d_in[4];
    const float* W2  = (const float*)d_in[5];
    const float* b2  = (const float*)d_in[6];
    const float* g2  = (const float*)d_in[7];
    const float* be2 = (const float*)d_in[8];
    const float* W3  = (const float*)d_in[9];
    const float* b3  = (const float*)d_in[10];
    const void*  np  = d_in[11];

    const int Bn = in_sizes[11];
    const int N  = in_sizes[0] / DIN;

    static const size_t SMEM_BYTES =
        (MT * PITCHH + MT * ZPH) * sizeof(__half)
        + (6 * HDIM + DOUT + 256 + 256 + 2 * MT) * sizeof(float)
        + MT * sizeof(int);
    cudaFuncSetAttribute(mlp_mma, cudaFuncAttributeMaxDynamicSharedMemorySize,
                         (int)SMEM_BYTES);

    int dev = 0, nsm = 148;
    cudaGetDevice(&dev);
    cudaDeviceGetAttribute(&nsm, cudaDevAttrMultiProcessorCount, dev);

    // mlp_mma kept as the 4th launch (ncu capture slot)
    scan_offsets<<<1, 256>>>(np, Bn);
    cvt_weights<<<64, 256>>>(W1, W2, W3);
    fill_seg_zero<<<Bn + (Bn * DOUT + 127) / 128, 128>>>(Bn);

    const int ntiles = (N + MT - 1) / MT;
    int grid = 2 * nsm;
    if (grid > ntiles) grid = ntiles;
    mlp_mma<<<grid, TPB, SMEM_BYTES>>>(z, b1, g1, be1, b2, g2, be2, b3, N, ntiles);

    const long long total4 = (long long)N * (DOUT / 4);
    broadcast_out<<<(int)((total4 + 255) / 256), 256>>>((float4*)d_out, total4);
}